// round 13
// baseline (speedup 1.0000x reference)
#include <cuda_runtime.h>
#include <cuda_fp16.h>
#include <math.h>
#include <stdint.h>

#define NEXP 64
#define KSEL 8
#define DDIM 1024
#define NCHUNK 32
#define S11 2048.0f
#define I11 4.8828125e-4f
#define STEP_STRIDE 1024
#define RT 21632
#define TT 1352
#define FT 1392
#define TPAIRS 888
#define FWARPS 592
#define NSLOT (2 * TT + FT)

__device__ float g_part[NSLOT * NEXP];
__device__ uint32_t Bfrag[NCHUNK * 2 * 2 * 8 * 64];
__device__ float wTd[DDIM * NEXP];

__device__ __forceinline__ uint32_t h2u(half2 h) {
    return *reinterpret_cast<uint32_t*>(&h);
}
__device__ __forceinline__ void split2(float2 v, uint32_t& h, uint32_t& l) {
    half2 hh = __float22half2_rn(v);
    float2 hb = __half22float2(hh);
    half2 ll = __float22half2_rn(
        make_float2((v.x - hb.x) * S11, (v.y - hb.y) * S11));
    h = h2u(hh);
    l = h2u(ll);
}

#define MMA_F16_ACC(cc, a, b0, b1)                                             \
    asm volatile(                                                              \
        "mma.sync.aligned.m16n8k16.row.col.f32.f16.f16.f32 "                   \
        "{%0,%1,%2,%3},{%4,%5,%6,%7},{%8,%9},{%0,%1,%2,%3};"                   \
        : "+f"((cc)[0]), "+f"((cc)[1]), "+f"((cc)[2]), "+f"((cc)[3])           \
        : "r"((a)[0]), "r"((a)[1]), "r"((a)[2]), "r"((a)[3]), "r"(b0), "r"(b1))
#define MMA_F16_NEW(dd, a, b0, b1)                                             \
    asm volatile(                                                              \
        "mma.sync.aligned.m16n8k16.row.col.f32.f16.f16.f32 "                   \
        "{%0,%1,%2,%3},{%4,%5,%6,%7},{%8,%9},{%10,%11,%12,%13};"               \
        : "=f"((dd)[0]), "=f"((dd)[1]), "=f"((dd)[2]), "=f"((dd)[3])           \
        : "r"((a)[0]), "r"((a)[1]), "r"((a)[2]), "r"((a)[3]), "r"(b0), "r"(b1),\
          "f"(0.0f), "f"(0.0f), "f"(0.0f), "f"(0.0f))
#define PBAR(id) asm volatile("bar.sync %0, 64;" :: "r"(id) : "memory")

// prep: split w into Bfrag AND transpose into wTd
__global__ void wprep_kernel(const float* __restrict__ w)
{
    int idx = blockIdx.x * 256 + threadIdx.x;     // 0..65535
    int e = idx >> 10, k = idx & 1023;
    wTd[k * NEXP + e] = w[idx];
    if (idx < 32768) {
        int n = idx >> 9, kp = idx & 511;
        float2 v = *(const float2*)(w + (size_t)n * DDIM + kp * 2);
        uint32_t h, l;
        split2(v, h, l);
        int kk = kp * 2;
        int ch = kk >> 5, win = kk & 31;
        int s = win >> 4, ki = win & 15;
        int sl = ki >> 3, q = (ki & 7) >> 1;
        int tile = n >> 3, lane = (n & 7) * 4 + q;
        uint32_t b = (uint32_t)(ch * 2 + s) * STEP_STRIDE + tile * 64 + lane * 2 + sl;
        Bfrag[b] = h;
        Bfrag[b + 512] = l;
    }
}

// epilogue for 8 rows, lanes 0..7 (caller guards lane<8)
__device__ __forceinline__ void epi8(
    const float* P, int rloc, int grow, int slot, int lane,
    const float* nw_s, const float* __restrict__ noise,
    float* __restrict__ out_w, float* __restrict__ out_ids)
{
    float L[64];
#pragma unroll
    for (int e = 0; e < 64; e++) L[e] = P[rloc * 65 + e];
    float m = -INFINITY;
#pragma unroll
    for (int e = 0; e < 64; e++) m = fmaxf(m, L[e]);
    float s = 0.f;
#pragma unroll
    for (int e = 0; e < 64; e++) s += __expf(L[e] - m);
    float sinv = 1.f / s;
    float ws[8];
#pragma unroll
    for (int e = 0; e < 64; e++) {
        float v = __expf(L[e] - m) * sinv;
        v += __shfl_xor_sync(0xffu, v, 4);
        v += __shfl_xor_sync(0xffu, v, 2);
        v += __shfl_xor_sync(0xffu, v, 1);
        if ((e & 7) == lane) ws[e >> 3] = v;
    }
#pragma unroll
    for (int q = 0; q < 8; q++)
        g_part[(size_t)slot * NEXP + q * 8 + lane] = ws[q];
    const float4* np = (const float4*)(noise + (size_t)grow * NEXP);
#pragma unroll
    for (int q = 0; q < 16; q++) {
        float4 nv = np[q];
        L[q * 4 + 0] = fmaf(nv.x, nw_s[q * 4 + 0], L[q * 4 + 0]);
        L[q * 4 + 1] = fmaf(nv.y, nw_s[q * 4 + 1], L[q * 4 + 1]);
        L[q * 4 + 2] = fmaf(nv.z, nw_s[q * 4 + 2], L[q * 4 + 2]);
        L[q * 4 + 3] = fmaf(nv.w, nw_s[q * 4 + 3], L[q * 4 + 3]);
    }
    float best[KSEL];
    int bid[KSEL];
    unsigned long long used = 0ull;
#pragma unroll
    for (int k = 0; k < KSEL; k++) {
        float mv = -INFINITY;
        int mi = 0;
#pragma unroll
        for (int e = 0; e < 64; e++) {
            bool ok = !((used >> e) & 1ull);
            if (ok && L[e] > mv) { mv = L[e]; mi = e; }
        }
        used |= 1ull << mi;
        best[k] = mv;
        bid[k] = mi;
    }
    float m0 = best[0], ss = 0.f;
#pragma unroll
    for (int k = 0; k < KSEL; k++) ss += __expf(best[k] - m0);
    float inv = 1.f / ss;
    float4 z = {0.f, 0.f, 0.f, 0.f};
    float4* ow = (float4*)(out_w + (size_t)grow * NEXP);
#pragma unroll
    for (int q = 0; q < 16; q++) ow[q] = z;
#pragma unroll
    for (int k = 0; k < KSEL; k++) {
        out_w[(size_t)grow * NEXP + bid[k]] = __expf(best[k] - m0) * inv;
        out_ids[(size_t)grow * KSEL + k] = (float)bid[k];
    }
}

__global__ void __launch_bounds__(512) gate_kernel(
    const float* __restrict__ x,
    const float* __restrict__ nw, const float* __restrict__ noise,
    float* __restrict__ out_w, float* __restrict__ out_ids)
{
    __shared__ __align__(16) float PT[6 * 1040];   // pair canvases 16x65
    __shared__ __align__(16) float PF[4 * 520];    // fma canvases 8x65
    __shared__ float nw_s[NEXP];

    const int tid = threadIdx.x, wid = tid >> 5, lane = tid & 31;
    if (tid < NEXP) nw_s[tid] = nw[tid];
    __syncthreads();

    if (wid < 12) {
        // ---------------- tensor pair unit ----------------
        const int pj = wid >> 1, eg = wid & 1;
        const int pGid = blockIdx.x * 6 + pj;
        float* const P = PT + pj * 1040;
        const int quad = lane & 3, r0 = lane >> 2;
        const uint32_t* const Bp = Bfrag + (uint32_t)(eg * 4) * 64 + lane * 2;

        for (int t = pGid; t < TT; t += TPAIRS) {
            const float* pA  = x + (size_t)(t * 16 + r0) * DDIM + quad * 2;
            const float* pA8 = pA + 8 * DDIM;
            float c0[4][4], c1[4][4];
#pragma unroll
            for (int u = 0; u < 4; u++)
#pragma unroll
                for (int i = 0; i < 4; i++) { c0[u][i] = 0.f; c1[u][i] = 0.f; }

#define LDA(ch, a) do {                                                        \
    _Pragma("unroll")                                                          \
    for (int _s2 = 0; _s2 < 2; _s2++) {                                        \
        *(float2*)&(a)[_s2 * 8 + 0] = *(const float2*)(pA  + (ch) * 32 + _s2 * 16);     \
        *(float2*)&(a)[_s2 * 8 + 2] = *(const float2*)(pA8 + (ch) * 32 + _s2 * 16);     \
        *(float2*)&(a)[_s2 * 8 + 4] = *(const float2*)(pA  + (ch) * 32 + _s2 * 16 + 8); \
        *(float2*)&(a)[_s2 * 8 + 6] = *(const float2*)(pA8 + (ch) * 32 + _s2 * 16 + 8); \
    }                                                                          \
} while (0)
#define CHUNK_BODY(ch, aC, aN) do {                                            \
    if ((ch) + 1 < NCHUNK) LDA((ch) + 1, aN);                                  \
    _Pragma("unroll")                                                          \
    for (int _s = 0; _s < 2; _s++) {                                           \
        uint32_t ah[4], al[4];                                                 \
        _Pragma("unroll")                                                      \
        for (int _i = 0; _i < 4; _i++)                                         \
            split2(*(float2*)&(aC)[_s * 8 + _i * 2], ah[_i], al[_i]);          \
        const uint32_t* bp = Bp + ((uint32_t)(ch) * 2 + _s) * STEP_STRIDE;     \
        _Pragma("unroll")                                                      \
        for (int _t = 0; _t < 4; _t++) {                                       \
            uint2 bh = *(const uint2*)(bp + _t * 64);                          \
            uint2 bl = *(const uint2*)(bp + _t * 64 + 512);                    \
            float dd[4];                                                       \
            MMA_F16_NEW(dd, ah, bh.x, bh.y);                                   \
            MMA_F16_ACC(c1[_t], ah, bl.x, bl.y);                               \
            MMA_F16_ACC(c1[_t], al, bh.x, bh.y);                               \
            c0[_t][0] += dd[0]; c0[_t][1] += dd[1];                            \
            c0[_t][2] += dd[2]; c0[_t][3] += dd[3];                            \
        }                                                                      \
    }                                                                          \
} while (0)
            float aCur[16], aNxt[16];
            LDA(0, aCur);
#pragma unroll 1
            for (int cc = 0; cc < NCHUNK; cc += 2) {
                CHUNK_BODY(cc, aCur, aNxt);
                CHUNK_BODY(cc + 1, aNxt, aCur);
            }
#pragma unroll
            for (int u = 0; u < 4; u++) {
                int cb = (eg * 4 + u) * 8 + 2 * quad;
#pragma unroll
                for (int i = 0; i < 4; i++) {
                    float v = fmaf(c1[u][i], I11, c0[u][i]);
                    P[(r0 + (i >> 1) * 8) * 65 + cb + (i & 1)] = v;
                }
            }
            PBAR(1 + pj);
            if (lane < 8)
                epi8(P, eg * 8 + lane, t * 16 + eg * 8 + lane, 2 * t + eg,
                     lane, nw_s, noise, out_w, out_ids);
            PBAR(1 + pj);
        }
    } else {
        // ---------------- fp32 FMA unit ----------------
        const int wf = wid - 12;
        const int fGid = blockIdx.x * 4 + wf;
        float* const P = PF + wf * 520;
        const int ty = lane >> 3, tx = lane & 7;

        for (int t = fGid; t < FT; t += FWARPS) {
            int gb = RT + t * 8;
            const float* xr0 = x + (size_t)(gb + ty * 2) * DDIM;
            const float* xr1 = xr0 + DDIM;
            float acc[2][8];
#pragma unroll
            for (int j = 0; j < 8; j++) { acc[0][j] = 0.f; acc[1][j] = 0.f; }
#pragma unroll 1
            for (int k0 = 0; k0 < DDIM; k0 += 4) {
                float4 a0 = *(const float4*)(xr0 + k0);
                float4 a1 = *(const float4*)(xr1 + k0);
                float av0[4] = {a0.x, a0.y, a0.z, a0.w};
                float av1[4] = {a1.x, a1.y, a1.z, a1.w};
#pragma unroll
                for (int kk = 0; kk < 4; kk++) {
                    const float* bp = wTd + (size_t)(k0 + kk) * NEXP + tx * 8;
                    float4 b0 = *(const float4*)bp;
                    float4 b1 = *(const float4*)(bp + 4);
                    float bv[8] = {b0.x, b0.y, b0.z, b0.w,
                                   b1.x, b1.y, b1.z, b1.w};
#pragma unroll
                    for (int j = 0; j < 8; j++) {
                        acc[0][j] = fmaf(av0[kk], bv[j], acc[0][j]);
                        acc[1][j] = fmaf(av1[kk], bv[j], acc[1][j]);
                    }
                }
            }
#pragma unroll
            for (int j = 0; j < 8; j++) {
                P[(ty * 2) * 65 + tx * 8 + j]     = acc[0][j];
                P[(ty * 2 + 1) * 65 + tx * 8 + j] = acc[1][j];
            }
            __syncwarp();
            if (lane < 8)
                epi8(P, lane, gb + lane, 2 * TT + t, lane, nw_s, noise,
                     out_w, out_ids);
            __syncwarp();
        }
    }
}

__global__ void __launch_bounds__(1024) loss_kernel(
    int nSlots, int N, float* __restrict__ out_loss)
{
    __shared__ double red[1024];
    const int t = threadIdx.x;
    const int e = t & 63, g = t >> 6;
    double s = 0.0;
    for (int b = g; b < nSlots; b += 16) s += (double)g_part[b * NEXP + e];
    red[t] = s;
    __syncthreads();
    for (int off = 512; off >= 64; off >>= 1) {
        if (t < off) red[t] += red[t + off];
        __syncthreads();
    }
    if (t < 64) {
        double d = red[t] / (double)N - 1.0 / 64.0;
        red[t] = d * d;
    }
    __syncthreads();
    for (int off = 32; off >= 1; off >>= 1) {
        if (t < off) red[t] += red[t + off];
        __syncthreads();
    }
    if (t == 0) *out_loss = (float)(red[0] / 64.0 * 0.01);
}

extern "C" void kernel_launch(void* const* d_in, const int* in_sizes, int n_in,
                              void* d_out, int out_size)
{
    const float* x     = (const float*)d_in[0];
    const float* w     = (const float*)d_in[1];
    const float* nw    = (const float*)d_in[2];
    const float* noise = (const float*)d_in[3];

    int N = in_sizes[3] / NEXP;   // 32768
    float* out      = (float*)d_out;
    float* out_w    = out;
    float* out_ids  = out + (size_t)N * NEXP;
    float* out_loss = out + (size_t)N * NEXP + (size_t)N * KSEL;

    wprep_kernel<<<256, 256>>>(w);
    gate_kernel<<<148, 512>>>(x, nw, noise, out_w, out_ids);
    loss_kernel<<<1, 1024>>>(NSLOT, N, out_loss);
}

// round 14
// speedup vs baseline: 4.5790x; 4.5790x over previous
#include <cuda_runtime.h>
#include <cuda_fp16.h>
#include <math.h>
#include <stdint.h>

#define NEXP 64
#define KSEL 8
#define DDIM 1024
#define MTILE 128
#define NCHUNK 32
#define MAXBLK 512
#define S11 2048.0f
#define I11 4.8828125e-4f
#define STEP_STRIDE 1024

__device__ float g_part[MAXBLK * NEXP];
__device__ uint32_t Bfrag[NCHUNK * 2 * 2 * 8 * 64];

__device__ __forceinline__ uint32_t h2u(half2 h) {
    return *reinterpret_cast<uint32_t*>(&h);
}
__device__ __forceinline__ void split2(float2 v, uint32_t& h, uint32_t& l) {
    half2 hh = __float22half2_rn(v);
    float2 hb = __half22float2(hh);
    half2 ll = __float22half2_rn(
        make_float2((v.x - hb.x) * S11, (v.y - hb.y) * S11));
    h = h2u(hh);
    l = h2u(ll);
}

#define MMA_F16_ACC(cc, a, b0, b1)                                             \
    asm volatile(                                                              \
        "mma.sync.aligned.m16n8k16.row.col.f32.f16.f16.f32 "                   \
        "{%0,%1,%2,%3},{%4,%5,%6,%7},{%8,%9},{%0,%1,%2,%3};"                   \
        : "+f"((cc)[0]), "+f"((cc)[1]), "+f"((cc)[2]), "+f"((cc)[3])           \
        : "r"((a)[0]), "r"((a)[1]), "r"((a)[2]), "r"((a)[3]), "r"(b0), "r"(b1))
#define MMA_F16_NEW(dd, a, b0, b1)                                             \
    asm volatile(                                                              \
        "mma.sync.aligned.m16n8k16.row.col.f32.f16.f16.f32 "                   \
        "{%0,%1,%2,%3},{%4,%5,%6,%7},{%8,%9},{%10,%11,%12,%13};"               \
        : "=f"((dd)[0]), "=f"((dd)[1]), "=f"((dd)[2]), "=f"((dd)[3])           \
        : "r"((a)[0]), "r"((a)[1]), "r"((a)[2]), "r"((a)[3]), "r"(b0), "r"(b1),\
          "f"(0.0f), "f"(0.0f), "f"(0.0f), "f"(0.0f))

__global__ void wsplit_kernel(const float* __restrict__ w)
{
    int idx = blockIdx.x * 256 + threadIdx.x;
    int n = idx >> 9;
    int kp = idx & 511;
    float2 v = *(const float2*)(w + (size_t)n * DDIM + kp * 2);
    uint32_t h, l;
    split2(v, h, l);
    int k = kp * 2;
    int ch = k >> 5, win = k & 31;
    int s = win >> 4, kk = win & 15;
    int sl = kk >> 3, q = (kk & 7) >> 1;
    int tile = n >> 3, lane = (n & 7) * 4 + q;
    uint32_t base = (uint32_t)(ch * 2 + s) * STEP_STRIDE + tile * 64 + lane * 2 + sl;
    Bfrag[base]       = h;
    Bfrag[base + 512] = l;
}

__global__ void __launch_bounds__(512) gate_kernel(
    const float* __restrict__ x,
    const float* __restrict__ nw, const float* __restrict__ noise,
    float* __restrict__ out_w, float* __restrict__ out_ids)
{
    __shared__ __align__(16) float U[128 * 65];
    __shared__ float nw_s[NEXP];
    __shared__ float wsum[4][NEXP];

    const int tid    = threadIdx.x;
    const int wid    = tid >> 5;
    const int lane   = tid & 31;
    const int quad   = lane & 3;
    const int r0     = lane >> 2;
    const int rowgrp = wid >> 1;
    const int eg     = wid & 1;
    const int base   = blockIdx.x * MTILE;

    if (tid < NEXP) nw_s[tid] = nw[tid];

    const float* pA  = x + (size_t)(base + rowgrp * 16 + r0) * DDIM + quad * 2;
    const float* pA8 = pA + 8 * DDIM;
    const uint32_t* const Bp = Bfrag + (uint32_t)(eg * 4) * 64 + lane * 2;

    float c0[4][4], c1[4][4];
#pragma unroll
    for (int t = 0; t < 4; t++)
#pragma unroll
        for (int i = 0; i < 4; i++) { c0[t][i] = 0.f; c1[t][i] = 0.f; }

#define LDA(ch, a) do {                                                        \
    _Pragma("unroll")                                                          \
    for (int _s2 = 0; _s2 < 2; _s2++) {                                        \
        *(float2*)&(a)[_s2 * 8 + 0] = *(const float2*)(pA  + (ch) * 32 + _s2 * 16);     \
        *(float2*)&(a)[_s2 * 8 + 2] = *(const float2*)(pA8 + (ch) * 32 + _s2 * 16);     \
        *(float2*)&(a)[_s2 * 8 + 4] = *(const float2*)(pA  + (ch) * 32 + _s2 * 16 + 8); \
        *(float2*)&(a)[_s2 * 8 + 6] = *(const float2*)(pA8 + (ch) * 32 + _s2 * 16 + 8); \
    }                                                                          \
} while (0)

// ILP-reordered k-step: same-accumulator MMA distance 4 (was 1 in R8);
// per-accumulator op order unchanged -> bit-identical results to R8.
#define CHUNK_BODY(ch, aC, aN) do {                                            \
    if ((ch) + 1 < NCHUNK) LDA((ch) + 1, aN);                                  \
    _Pragma("unroll")                                                          \
    for (int _s = 0; _s < 2; _s++) {                                           \
        uint32_t ah[4], al[4];                                                 \
        _Pragma("unroll")                                                      \
        for (int _i = 0; _i < 4; _i++)                                         \
            split2(*(float2*)&(aC)[_s * 8 + _i * 2], ah[_i], al[_i]);          \
        const uint32_t* bp = Bp + ((uint32_t)(ch) * 2 + _s) * STEP_STRIDE;     \
        float dd[4][4];                                                        \
        _Pragma("unroll")                                                      \
        for (int _t = 0; _t < 4; _t++) {                                       \
            uint2 bh = *(const uint2*)(bp + _t * 64);                          \
            MMA_F16_NEW(dd[_t], ah, bh.x, bh.y);                               \
        }                                                                      \
        _Pragma("unroll")                                                      \
        for (int _t = 0; _t < 4; _t++) {                                       \
            uint2 bl = *(const uint2*)(bp + _t * 64 + 512);                    \
            MMA_F16_ACC(c1[_t], ah, bl.x, bl.y);                               \
        }                                                                      \
        _Pragma("unroll")                                                      \
        for (int _t = 0; _t < 4; _t++) {                                       \
            uint2 bh = *(const uint2*)(bp + _t * 64);                          \
            MMA_F16_ACC(c1[_t], al, bh.x, bh.y);                               \
        }                                                                      \
        _Pragma("unroll")                                                      \
        for (int _t = 0; _t < 4; _t++) {                                       \
            c0[_t][0] += dd[_t][0]; c0[_t][1] += dd[_t][1];                    \
            c0[_t][2] += dd[_t][2]; c0[_t][3] += dd[_t][3];                    \
        }                                                                      \
    }                                                                          \
} while (0)

    float aCur[16], aNxt[16];
    LDA(0, aCur);
#pragma unroll 1
    for (int cc = 0; cc < NCHUNK; cc += 2) {
        CHUNK_BODY(cc, aCur, aNxt);
        CHUNK_BODY(cc + 1, aNxt, aCur);
    }

    {
        int rA = rowgrp * 16 + r0;
#pragma unroll
        for (int t = 0; t < 4; t++) {
            int cb = (eg * 4 + t) * 8 + 2 * quad;
#pragma unroll
            for (int i = 0; i < 4; i++) {
                float v = fmaf(c1[t][i], I11, c0[t][i]);
                int rr = rA + (i >> 1) * 8;
                U[rr * 65 + cb + (i & 1)] = v;
            }
        }
    }
    __syncthreads();

    if (tid < 128) {
        const int r = tid;
        float L[64];
#pragma unroll
        for (int e = 0; e < 64; e++) L[e] = U[r * 65 + e];

        float m = -INFINITY;
#pragma unroll
        for (int e = 0; e < 64; e++) m = fmaxf(m, L[e]);
        float s = 0.f;
#pragma unroll
        for (int e = 0; e < 64; e++) s += __expf(L[e] - m);
        float sinv = 1.f / s;

#pragma unroll
        for (int e = 0; e < 64; e++) {
            float v = __expf(L[e] - m) * sinv;
            v += __shfl_xor_sync(0xffffffffu, v, 16);
            v += __shfl_xor_sync(0xffffffffu, v, 8);
            v += __shfl_xor_sync(0xffffffffu, v, 4);
            v += __shfl_xor_sync(0xffffffffu, v, 2);
            v += __shfl_xor_sync(0xffffffffu, v, 1);
            if ((e & 31) == lane) wsum[wid][e] = v;
        }

        const float4* np = (const float4*)(noise + (size_t)(base + r) * NEXP);
#pragma unroll
        for (int q = 0; q < 16; q++) {
            float4 nv = np[q];
            L[q * 4 + 0] = fmaf(nv.x, nw_s[q * 4 + 0], L[q * 4 + 0]);
            L[q * 4 + 1] = fmaf(nv.y, nw_s[q * 4 + 1], L[q * 4 + 1]);
            L[q * 4 + 2] = fmaf(nv.z, nw_s[q * 4 + 2], L[q * 4 + 2]);
            L[q * 4 + 3] = fmaf(nv.w, nw_s[q * 4 + 3], L[q * 4 + 3]);
        }

        float best[KSEL];
        int bid[KSEL];
        unsigned long long used = 0ull;
#pragma unroll
        for (int k = 0; k < KSEL; k++) {
            float mv = -INFINITY;
            int mi = 0;
#pragma unroll
            for (int e = 0; e < 64; e++) {
                bool ok = !((used >> e) & 1ull);
                if (ok && L[e] > mv) { mv = L[e]; mi = e; }
            }
            used |= 1ull << mi;
            best[k] = mv;
            bid[k] = mi;
        }
        float m0 = best[0];
        float ss = 0.f;
#pragma unroll
        for (int k = 0; k < KSEL; k++) ss += __expf(best[k] - m0);
        float inv = 1.f / ss;

        float4 z = {0.f, 0.f, 0.f, 0.f};
        float4* ow = (float4*)(out_w + (size_t)(base + r) * NEXP);
#pragma unroll
        for (int q = 0; q < 16; q++) ow[q] = z;
#pragma unroll
        for (int k = 0; k < KSEL; k++) {
            out_w[(size_t)(base + r) * NEXP + bid[k]] = __expf(best[k] - m0) * inv;
            out_ids[(size_t)(base + r) * KSEL + k] = (float)bid[k];
        }
    }
    __syncthreads();
    if (tid < NEXP)
        g_part[blockIdx.x * NEXP + tid] =
            wsum[0][tid] + wsum[1][tid] + wsum[2][tid] + wsum[3][tid];
}

__global__ void __launch_bounds__(1024) loss_kernel(
    int nBlocks, int N, float* __restrict__ out_loss)
{
    __shared__ double red[1024];
    const int t = threadIdx.x;
    const int e = t & 63, g = t >> 6;
    double s = 0.0;
    for (int b = g; b < nBlocks; b += 16) s += (double)g_part[b * NEXP + e];
    red[t] = s;
    __syncthreads();
    for (int off = 512; off >= 64; off >>= 1) {
        if (t < off) red[t] += red[t + off];
        __syncthreads();
    }
    if (t < 64) {
        double d = red[t] / (double)N - 1.0 / 64.0;
        red[t] = d * d;
    }
    __syncthreads();
    for (int off = 32; off >= 1; off >>= 1) {
        if (t < off) red[t] += red[t + off];
        __syncthreads();
    }
    if (t == 0) *out_loss = (float)(red[0] / 64.0 * 0.01);
}

extern "C" void kernel_launch(void* const* d_in, const int* in_sizes, int n_in,
                              void* d_out, int out_size)
{
    const float* x     = (const float*)d_in[0];  // [N, 1024]
    const float* w     = (const float*)d_in[1];  // [64, 1024]
    const float* nw    = (const float*)d_in[2];  // [64]
    const float* noise = (const float*)d_in[3];  // [N, 64]

    int N = in_sizes[3] / NEXP;
    int nBlocks = N / MTILE;

    float* out      = (float*)d_out;
    float* out_w    = out;
    float* out_ids  = out + (size_t)N * NEXP;
    float* out_loss = out + (size_t)N * NEXP + (size_t)N * KSEL;

    wsplit_kernel<<<128, 256>>>(w);
    gate_kernel<<<nBlocks, 512>>>(x, nw, noise, out_w, out_ids);
    loss_kernel<<<1, 1024>>>(nBlocks, N, out_loss);
}